// round 16
// baseline (speedup 1.0000x reference)
#include <cuda_runtime.h>

#define Bn 128
#define Tn 256
#define Cn 384
#define Hn 64
#define Mtot (Bn*Tn)   // 32768 rows

typedef unsigned int u32;
typedef unsigned short u16;

// q,k,v scratch in fp16 (k pre-scaled by 384^-0.5*log2e via W prepass)
__device__ u16 g_qh[Mtot*Hn];
__device__ u16 g_kh[Mtot*Hn];
__device__ u16 g_vh[Mtot*Hn];
// W pre-converted to fp16, fused layout [384][192] = q|k|v, k-scale folded
__device__ u16 g_wh[Cn*192];

// ---------------------------------------------------------------------------
// helpers
// ---------------------------------------------------------------------------
__device__ __forceinline__ u32 sptr(const void* p) {
    return (u32)__cvta_generic_to_shared(p);
}
__device__ __forceinline__ void ldm4(u32& r0, u32& r1, u32& r2, u32& r3, u32 a) {
    asm volatile("ldmatrix.sync.aligned.m8n8.x4.shared.b16 {%0,%1,%2,%3},[%4];"
                 : "=r"(r0), "=r"(r1), "=r"(r2), "=r"(r3) : "r"(a));
}
__device__ __forceinline__ void ldm4t(u32& r0, u32& r1, u32& r2, u32& r3, u32 a) {
    asm volatile("ldmatrix.sync.aligned.m8n8.x4.trans.shared.b16 {%0,%1,%2,%3},[%4];"
                 : "=r"(r0), "=r"(r1), "=r"(r2), "=r"(r3) : "r"(a));
}
__device__ __forceinline__ void mma_f16(float* c, const u32* a, const u32* b) {
    asm volatile(
        "mma.sync.aligned.m16n8k16.row.col.f32.f16.f16.f32 "
        "{%0,%1,%2,%3},{%4,%5,%6,%7},{%8,%9},{%0,%1,%2,%3};"
        : "+f"(c[0]), "+f"(c[1]), "+f"(c[2]), "+f"(c[3])
        : "r"(a[0]), "r"(a[1]), "r"(a[2]), "r"(a[3]), "r"(b[0]), "r"(b[1]));
}
// fp16 pack: elem a -> lower half, b -> upper half
__device__ __forceinline__ u32 pack_h2(float a, float b) {
    u32 r; asm("cvt.rn.f16x2.f32 %0,%1,%2;" : "=r"(r) : "f"(b), "f"(a)); return r;
}
__device__ __forceinline__ float ex2(float x) {
    float y; asm("ex2.approx.ftz.f32 %0,%1;" : "=f"(y) : "f"(x)); return y;
}
__device__ __forceinline__ void cpa16(u32 dst, const void* src) {
    asm volatile("cp.async.cg.shared.global [%0],[%1],16;" :: "r"(dst), "l"(src));
}
__device__ __forceinline__ void cpa_commit() { asm volatile("cp.async.commit_group;"); }
__device__ __forceinline__ void cpa_wait_all() { asm volatile("cp.async.wait_group 0;"); }

// ---------------------------------------------------------------------------
// W prepass: [384][64]x3 fp32 -> fused fp16 [384][192], k-scale folded.
// ---------------------------------------------------------------------------
__global__ void conv_w(const float* __restrict__ Wq,
                       const float* __restrict__ Wk,
                       const float* __restrict__ Wv)
{
    const float SCL = 0.051031036307982884f * 1.4426950408889634f;
    int base = blockIdx.x * 256 + threadIdx.x;
    #pragma unroll
    for (int j = 0; j < 2; j++) {
        int i = base + j * 18432;             // 0..36863 (u32 pairs)
        int e = i * 2;
        int k = e / 192, n = e % 192;         // n even; pair never crosses a row
        const float* W = (n < 64) ? Wq : (n < 128) ? Wk : Wv;
        float a = W[k * 64 + (n & 63)];
        float b = W[k * 64 + ((n + 1) & 63)];
        float s = (n >= 64 && n < 128) ? SCL : 1.0f;
        *(u32*)&g_wh[e] = pack_h2(a * s, b * s);
    }
}

// ---------------------------------------------------------------------------
// Fused QKV projection; now __launch_bounds__(256,3) for 24 warps/SM.
// ---------------------------------------------------------------------------
__global__ __launch_bounds__(256, 3) void qkv_fused(const float* __restrict__ x)
{
    __shared__ __align__(16) u16 Xs[2][64 * 40];
    __shared__ __align__(16) u16 Ws[2][32 * 200];

    const int tid    = threadIdx.x;
    const int lane   = tid & 31;
    const int wid    = tid >> 5;
    const int warp_m = wid >> 2;          // 0..1
    const int warp_n = wid & 3;           // 0..3
    const int g4     = lane >> 2;
    const int t4     = lane & 3;
    const int m0     = blockIdx.x * 64;

    const int r8  = lane & 7;
    const int sel = lane >> 3;
    const int a_row = (sel & 1) * 8 + r8;
    const int a_kof = (sel >> 1) * 8;
    const int b_krow = (sel & 1) * 8 + r8;
    const int b_nof  = (sel >> 1) * 8;

    const int xrow = tid >> 3, xcg = tid & 7;
    int wro[3], wc16[3];
    #pragma unroll
    for (int i = 0; i < 3; i++) {
        int idx = tid + i * 256;
        wro[i] = idx / 24;
        wc16[i] = idx % 24;
    }

    float acc[2][6][4];
    #pragma unroll
    for (int mt = 0; mt < 2; mt++)
        #pragma unroll
        for (int nt = 0; nt < 6; nt++)
            #pragma unroll
            for (int e = 0; e < 4; e++) acc[mt][nt][e] = 0.f;

    float4 xv[2];

    auto loadX = [&](int kb) {
        #pragma unroll
        for (int i = 0; i < 2; i++)
            xv[i] = *(const float4*)(x + (size_t)(m0 + xrow + i * 32) * Cn + kb + xcg * 4);
    };
    auto stsX = [&](int p) {
        #pragma unroll
        for (int i = 0; i < 2; i++)
            *(uint2*)&Xs[p][(xrow + i * 32) * 40 + xcg * 4] =
                make_uint2(pack_h2(xv[i].x, xv[i].y), pack_h2(xv[i].z, xv[i].w));
    };
    auto stageW = [&](int kt, int p) {
        u32 dst = sptr(Ws[p]);
        #pragma unroll
        for (int i = 0; i < 3; i++)
            cpa16(dst + 2u * (wro[i] * 200 + wc16[i] * 8),
                  g_wh + (size_t)(kt * 32 + wro[i]) * 192 + wc16[i] * 8);
        cpa_commit();
    };

    stageW(0, 0);
    loadX(0);
    stsX(0);
    cpa_wait_all();
    __syncthreads();

    for (int kt = 0; kt < 12; kt++) {
        const int p = kt & 1;
        if (kt < 11) {
            loadX((kt + 1) * 32);
            stageW(kt + 1, p ^ 1);
        }

        const u32 XsS = sptr(Xs[p]);
        const u32 WsS = sptr(Ws[p]);
        #pragma unroll
        for (int ks = 0; ks < 2; ks++) {
            const int k0 = ks * 16;
            u32 a[2][4];
            #pragma unroll
            for (int mt = 0; mt < 2; mt++) {
                u32 off = 2u * ((warp_m * 32 + mt * 16 + a_row) * 40 + k0 + a_kof);
                ldm4(a[mt][0], a[mt][1], a[mt][2], a[mt][3], XsS + off);
            }
            u32 bw[3][4];
            #pragma unroll
            for (int h = 0; h < 3; h++) {
                u32 off = 2u * ((k0 + b_krow) * 200 + warp_n * 48 + h * 16 + b_nof);
                ldm4t(bw[h][0], bw[h][1], bw[h][2], bw[h][3], WsS + off);
            }
            #pragma unroll
            for (int mt = 0; mt < 2; mt++)
                #pragma unroll
                for (int h = 0; h < 3; h++)
                    #pragma unroll
                    for (int j = 0; j < 2; j++)
                        mma_f16(acc[mt][h * 2 + j], a[mt], &bw[h][2 * j]);
        }

        if (kt < 11) {
            stsX(p ^ 1);
            cpa_wait_all();
        }
        __syncthreads();
    }

    #pragma unroll
    for (int mt = 0; mt < 2; mt++) {
        int row = m0 + warp_m * 32 + mt * 16 + g4;
        #pragma unroll
        for (int nt = 0; nt < 6; nt++) {
            int n = warp_n * 48 + nt * 8;
            u16* outp = (n < 64) ? g_qh : (n < 128) ? g_kh : g_vh;
            int col = (n & 63) + 2 * t4;
            *(u32*)&outp[(size_t)row       * Hn + col] =
                pack_h2(acc[mt][nt][0], acc[mt][nt][1]);
            *(u32*)&outp[(size_t)(row + 8) * Hn + col] =
                pack_h2(acc[mt][nt][2], acc[mt][nt][3]);
        }
    }
}

// ---------------------------------------------------------------------------
// Fused causal attention v5: as R15 but __launch_bounds__(256,4) -> 4 CTAs/SM
// (32 warps; smem 4x55.8KB = 218KB fits). Arithmetic bit-identical.
// ---------------------------------------------------------------------------
#define ATTN_SMEM (6 * 9216 + 128 * 4)

__global__ __launch_bounds__(256, 4) void attn_f16(float* __restrict__ out)
{
    extern __shared__ __align__(16) char smc[];
    u16* Ks = (u16*)smc;                       // [64][72]
    u16* Qs[2] = { (u16*)(smc + 9216),     (u16*)(smc + 2 * 9216) };
    u16* Vs[2] = { (u16*)(smc + 3 * 9216), (u16*)(smc + 4 * 9216) };
    u16* Ps = (u16*)(smc + 5 * 9216);
    float* pm = (float*)(smc + 6 * 9216);      // [128]

    const int tid  = threadIdx.x;
    const int lane = tid & 31;
    const int wid  = tid >> 5;
    const int warp_m = wid >> 1;        // 0..3
    const int warp_n = wid & 1;         // 0..1
    const int g4 = lane >> 2;
    const int t4 = lane & 3;
    const int r8  = lane & 7;
    const int sel = lane >> 3;
    const int a_row = (sel & 1) * 8 + r8;
    const int a_kof = (sel >> 1) * 8;
    const int bt_krow = (sel & 1) * 8 + r8;
    const int bt_nof  = (sel >> 1) * 8;
    const int bn_row = (sel >> 1) * 8 + r8;
    const int bn_kof = (sel & 1) * 8;

    const int qt = 3 - blockIdx.x;      // heavy tiles first
    const int b  = blockIdx.y;
    const int rowg0 = b * Tn + qt * 64;

    const u32 KsS = sptr(Ks), PsS = sptr(Ps);
    const u32 QsS[2] = { sptr(Qs[0]), sptr(Qs[1]) };
    const u32 VsS[2] = { sptr(Vs[0]), sptr(Vs[1]) };

    const int srow = tid >> 3, scg = tid & 7;

    // ---- prologue: stage K + Q0 + V0 via cp.async ----
    #pragma unroll
    for (int i = 0; i < 2; i++) {
        int r = srow + i * 32;
        u32 o2 = 2u * (r * 72 + scg * 8);
        cpa16(KsS + o2,    g_kh + (size_t)(rowg0 + r) * Hn + scg * 8);
        size_t g0 = (size_t)(b * Tn + r) * Hn + scg * 8;
        cpa16(QsS[0] + o2, g_qh + g0);
        cpa16(VsS[0] + o2, g_vh + g0);
    }
    cpa_commit();
    cpa_wait_all();
    __syncthreads();

    const int r0loc = warp_m * 16 + g4;
    float l0 = 0.f, l1 = 0.f;
    float oacc[4][4];
    #pragma unroll
    for (int nt = 0; nt < 4; nt++)
        #pragma unroll
        for (int e = 0; e < 4; e++) oacc[nt][e] = 0.f;

    for (int st = 0; st <= qt; st++) {
        const int p = st & 1;

        // prefetch next Q/V tile via cp.async (hidden under compute)
        if (st < qt) {
            #pragma unroll
            for (int i = 0; i < 2; i++) {
                int r = srow + i * 32;
                u32 o2 = 2u * (r * 72 + scg * 8);
                size_t g = (size_t)(b * Tn + (st + 1) * 64 + r) * Hn + scg * 8;
                cpa16(QsS[p ^ 1] + o2, g_qh + g);
                cpa16(VsS[p ^ 1] + o2, g_vh + g);
            }
            cpa_commit();
        }

        // ---- S = K . Q^T ----
        float sv[4][4];
        #pragma unroll
        for (int nt = 0; nt < 4; nt++)
            #pragma unroll
            for (int e = 0; e < 4; e++) sv[nt][e] = 0.f;

        #pragma unroll
        for (int ks = 0; ks < 4; ks++) {
            const int k0 = ks * 16;
            u32 a[4];
            u32 aoff = 2u * ((warp_m * 16 + a_row) * 72 + k0 + a_kof);
            ldm4(a[0], a[1], a[2], a[3], KsS + aoff);
            #pragma unroll
            for (int h = 0; h < 2; h++) {
                u32 bq[4];
                u32 boff = 2u * ((warp_n * 32 + h * 16 + bn_row) * 72 + k0 + bn_kof);
                ldm4(bq[0], bq[1], bq[2], bq[3], QsS[p] + boff);
                #pragma unroll
                for (int j = 0; j < 2; j++)
                    mma_f16(sv[h * 2 + j], a, &bq[2 * j]);
            }
        }

        // ---- causal mask on diagonal tile ----
        if (st == qt) {
            #pragma unroll
            for (int nt = 0; nt < 4; nt++) {
                int col = warp_n * 32 + nt * 8 + 2 * t4;
                if (col     > r0loc)     sv[nt][0] = -1e30f;
                if (col + 1 > r0loc)     sv[nt][1] = -1e30f;
                if (col     > r0loc + 8) sv[nt][2] = -1e30f;
                if (col + 1 > r0loc + 8) sv[nt][3] = -1e30f;
            }
        }

        // ---- p = 2^s (fixed m=0), accumulate l, write P ----
        #pragma unroll
        for (int nt = 0; nt < 4; nt++) {
            float p0 = ex2(sv[nt][0]);
            float p1 = ex2(sv[nt][1]);
            float p2 = ex2(sv[nt][2]);
            float p3 = ex2(sv[nt][3]);
            l0 += p0 + p1; l1 += p2 + p3;
            int col = warp_n * 32 + nt * 8 + 2 * t4;
            *(u32*)&Ps[r0loc * 72 + col]       = pack_h2(p0, p1);
            *(u32*)&Ps[(r0loc + 8) * 72 + col] = pack_h2(p2, p3);
        }
        // P visibility within the warp_m pair
        asm volatile("bar.sync %0, %1;" :: "r"(1 + warp_m), "r"(64) : "memory");

        // ---- O += P @ V ----
        #pragma unroll
        for (int ks = 0; ks < 4; ks++) {
            const int k0 = ks * 16;
            u32 a[4];
            u32 aoff = 2u * ((warp_m * 16 + a_row) * 72 + k0 + a_kof);
            ldm4(a[0], a[1], a[2], a[3], PsS + aoff);
            #pragma unroll
            for (int h = 0; h < 2; h++) {
                u32 bv[4];
                u32 boff = 2u * ((k0 + bt_krow) * 72 + warp_n * 32 + h * 16 + bt_nof);
                ldm4t(bv[0], bv[1], bv[2], bv[3], VsS[p] + boff);
                #pragma unroll
                for (int j = 0; j < 2; j++)
                    mma_f16(oacc[h * 2 + j], a, &bv[2 * j]);
            }
        }

        if (st < qt) cpa_wait_all();   // next Q/V landed
        __syncthreads();               // P reads done; buffers consistent
    }

    // ---- epilogue: reduce l across t4 and warp_n, divide, store ----
    l0 += __shfl_xor_sync(0xffffffffu, l0, 1);
    l0 += __shfl_xor_sync(0xffffffffu, l0, 2);
    l1 += __shfl_xor_sync(0xffffffffu, l1, 1);
    l1 += __shfl_xor_sync(0xffffffffu, l1, 2);
    if (t4 == 0) {
        pm[warp_n * 64 + r0loc]     = l0;
        pm[warp_n * 64 + r0loc + 8] = l1;
    }
    __syncthreads();
    float inv0 = 1.f / (pm[r0loc]     + pm[64 + r0loc]);
    float inv1 = 1.f / (pm[r0loc + 8] + pm[64 + r0loc + 8]);

    #pragma unroll
    for (int nt = 0; nt < 4; nt++) {
        int col = warp_n * 32 + nt * 8 + 2 * t4;
        *(float2*)(out + (size_t)(rowg0 + r0loc)     * Hn + col) =
            make_float2(oacc[nt][0] * inv0, oacc[nt][1] * inv0);
        *(float2*)(out + (size_t)(rowg0 + r0loc + 8) * Hn + col) =
            make_float2(oacc[nt][2] * inv1, oacc[nt][3] * inv1);
    }
}

// ---------------------------------------------------------------------------
extern "C" void kernel_launch(void* const* d_in, const int* in_sizes, int n_in,
                              void* d_out, int out_size)
{
    const float* x  = (const float*)d_in[0];
    const float* Wq = (const float*)d_in[1];
    const float* Wk = (const float*)d_in[2];
    const float* Wv = (const float*)d_in[3];
    float* out = (float*)d_out;

    cudaFuncSetAttribute(attn_f16, cudaFuncAttributeMaxDynamicSharedMemorySize, ATTN_SMEM);

    conv_w<<<72, 256>>>(Wq, Wk, Wv);
    qkv_fused<<<512, 256>>>(x);
    attn_f16<<<dim3(4, Bn), 256, ATTN_SMEM>>>(out);
}

// round 17
// speedup vs baseline: 1.1405x; 1.1405x over previous
#include <cuda_runtime.h>

#define Bn 128
#define Tn 256
#define Cn 384
#define Hn 64
#define Mtot (Bn*Tn)   // 32768 rows

typedef unsigned int u32;
typedef unsigned short u16;

// q,k,v scratch in fp16 (k pre-scaled by 384^-0.5*log2e via W prepass)
__device__ u16 g_qh[Mtot*Hn];
__device__ u16 g_kh[Mtot*Hn];
__device__ u16 g_vh[Mtot*Hn];
// W pre-converted to fp16, fused layout [384][192] = q|k|v, k-scale folded
__device__ u16 g_wh[Cn*192];

// ---------------------------------------------------------------------------
// helpers
// ---------------------------------------------------------------------------
__device__ __forceinline__ u32 sptr(const void* p) {
    return (u32)__cvta_generic_to_shared(p);
}
__device__ __forceinline__ void ldm4(u32& r0, u32& r1, u32& r2, u32& r3, u32 a) {
    asm volatile("ldmatrix.sync.aligned.m8n8.x4.shared.b16 {%0,%1,%2,%3},[%4];"
                 : "=r"(r0), "=r"(r1), "=r"(r2), "=r"(r3) : "r"(a));
}
__device__ __forceinline__ void ldm4t(u32& r0, u32& r1, u32& r2, u32& r3, u32 a) {
    asm volatile("ldmatrix.sync.aligned.m8n8.x4.trans.shared.b16 {%0,%1,%2,%3},[%4];"
                 : "=r"(r0), "=r"(r1), "=r"(r2), "=r"(r3) : "r"(a));
}
__device__ __forceinline__ void mma_f16(float* c, const u32* a, const u32* b) {
    asm volatile(
        "mma.sync.aligned.m16n8k16.row.col.f32.f16.f16.f32 "
        "{%0,%1,%2,%3},{%4,%5,%6,%7},{%8,%9},{%0,%1,%2,%3};"
        : "+f"(c[0]), "+f"(c[1]), "+f"(c[2]), "+f"(c[3])
        : "r"(a[0]), "r"(a[1]), "r"(a[2]), "r"(a[3]), "r"(b[0]), "r"(b[1]));
}
// fp16 pack: elem a -> lower half, b -> upper half
__device__ __forceinline__ u32 pack_h2(float a, float b) {
    u32 r; asm("cvt.rn.f16x2.f32 %0,%1,%2;" : "=r"(r) : "f"(b), "f"(a)); return r;
}
__device__ __forceinline__ float ex2(float x) {
    float y; asm("ex2.approx.ftz.f32 %0,%1;" : "=f"(y) : "f"(x)); return y;
}
__device__ __forceinline__ void cpa16(u32 dst, const void* src) {
    asm volatile("cp.async.cg.shared.global [%0],[%1],16;" :: "r"(dst), "l"(src));
}
__device__ __forceinline__ void cpa_commit() { asm volatile("cp.async.commit_group;"); }
__device__ __forceinline__ void cpa_wait_all() { asm volatile("cp.async.wait_group 0;"); }

// ---------------------------------------------------------------------------
// W prepass: [384][64]x3 fp32 -> fused fp16 [384][192], k-scale folded.
// ---------------------------------------------------------------------------
__global__ void conv_w(const float* __restrict__ Wq,
                       const float* __restrict__ Wk,
                       const float* __restrict__ Wv)
{
    const float SCL = 0.051031036307982884f * 1.4426950408889634f;
    int base = blockIdx.x * 256 + threadIdx.x;
    #pragma unroll
    for (int j = 0; j < 2; j++) {
        int i = base + j * 18432;             // 0..36863 (u32 pairs)
        int e = i * 2;
        int k = e / 192, n = e % 192;         // n even; pair never crosses a row
        const float* W = (n < 64) ? Wq : (n < 128) ? Wk : Wv;
        float a = W[k * 64 + (n & 63)];
        float b = W[k * 64 + ((n + 1) & 63)];
        float s = (n >= 64 && n < 128) ? SCL : 1.0f;
        *(u32*)&g_wh[e] = pack_h2(a * s, b * s);
    }
}

// ---------------------------------------------------------------------------
// Fused QKV projection v2: 384 threads = 12 warps 2(M)x6(N), warp tile 32x32
// (32 acc regs -> ~70 total, 2 CTAs/SM = 24 warps without spills).
// Block tile 64x192, K-tile 32 double-buffered, 1 sync/K-tile.
// Accumulation order per output element identical to R15 -> bit-identical.
// ---------------------------------------------------------------------------
__global__ __launch_bounds__(384, 2) void qkv_fused(const float* __restrict__ x)
{
    __shared__ __align__(16) u16 Xs[2][64 * 40];
    __shared__ __align__(16) u16 Ws[2][32 * 200];

    const int tid    = threadIdx.x;
    const int lane   = tid & 31;
    const int wid    = tid >> 5;          // 0..11
    const int warp_m = wid / 6;           // 0..1
    const int warp_n = wid % 6;           // 0..5
    const int g4     = lane >> 2;
    const int t4     = lane & 3;
    const int m0     = blockIdx.x * 64;

    const int r8  = lane & 7;
    const int sel = lane >> 3;
    const int a_row = (sel & 1) * 8 + r8;
    const int a_kof = (sel >> 1) * 8;
    const int b_krow = (sel & 1) * 8 + r8;
    const int b_nof  = (sel >> 1) * 8;

    // X staging: 64x32 fp32 = 512 float4 chunks; thread takes tid and (tid<128) tid+384
    const int xr0 = tid >> 3,         xg0 = tid & 7;
    const int xr1 = (tid + 384) >> 3, xg1 = (tid + 384) & 7;
    const bool xok = tid < 128;
    // W staging: 32 rows x 24 chunks(16B) = 768 chunks, 2/thread
    int wro[2], wc16[2];
    #pragma unroll
    for (int i = 0; i < 2; i++) {
        int idx = tid + i * 384;
        wro[i] = idx / 24;
        wc16[i] = idx % 24;
    }

    float acc[2][4][4];
    #pragma unroll
    for (int mt = 0; mt < 2; mt++)
        #pragma unroll
        for (int nt = 0; nt < 4; nt++)
            #pragma unroll
            for (int e = 0; e < 4; e++) acc[mt][nt][e] = 0.f;

    float4 xv[2];

    auto loadX = [&](int kb) {
        xv[0] = *(const float4*)(x + (size_t)(m0 + xr0) * Cn + kb + xg0 * 4);
        if (xok)
            xv[1] = *(const float4*)(x + (size_t)(m0 + xr1) * Cn + kb + xg1 * 4);
    };
    auto stsX = [&](int p) {
        *(uint2*)&Xs[p][xr0 * 40 + xg0 * 4] =
            make_uint2(pack_h2(xv[0].x, xv[0].y), pack_h2(xv[0].z, xv[0].w));
        if (xok)
            *(uint2*)&Xs[p][xr1 * 40 + xg1 * 4] =
                make_uint2(pack_h2(xv[1].x, xv[1].y), pack_h2(xv[1].z, xv[1].w));
    };
    auto stageW = [&](int kt, int p) {
        u32 dst = sptr(Ws[p]);
        #pragma unroll
        for (int i = 0; i < 2; i++)
            cpa16(dst + 2u * (wro[i] * 200 + wc16[i] * 8),
                  g_wh + (size_t)(kt * 32 + wro[i]) * 192 + wc16[i] * 8);
        cpa_commit();
    };

    stageW(0, 0);
    loadX(0);
    stsX(0);
    cpa_wait_all();
    __syncthreads();

    for (int kt = 0; kt < 12; kt++) {
        const int p = kt & 1;
        if (kt < 11) {
            loadX((kt + 1) * 32);
            stageW(kt + 1, p ^ 1);
        }

        const u32 XsS = sptr(Xs[p]);
        const u32 WsS = sptr(Ws[p]);
        #pragma unroll
        for (int ks = 0; ks < 2; ks++) {
            const int k0 = ks * 16;
            u32 a[2][4];
            #pragma unroll
            for (int mt = 0; mt < 2; mt++) {
                u32 off = 2u * ((warp_m * 32 + mt * 16 + a_row) * 40 + k0 + a_kof);
                ldm4(a[mt][0], a[mt][1], a[mt][2], a[mt][3], XsS + off);
            }
            u32 bw[2][4];
            #pragma unroll
            for (int h = 0; h < 2; h++) {
                u32 off = 2u * ((k0 + b_krow) * 200 + warp_n * 32 + h * 16 + b_nof);
                ldm4t(bw[h][0], bw[h][1], bw[h][2], bw[h][3], WsS + off);
            }
            #pragma unroll
            for (int mt = 0; mt < 2; mt++)
                #pragma unroll
                for (int h = 0; h < 2; h++)
                    #pragma unroll
                    for (int j = 0; j < 2; j++)
                        mma_f16(acc[mt][h * 2 + j], a[mt], &bw[h][2 * j]);
        }

        if (kt < 11) {
            stsX(p ^ 1);
            cpa_wait_all();
        }
        __syncthreads();
    }

    // epilogue: scatter to q|k|v fp16 (k pre-scaled via W)
    #pragma unroll
    for (int mt = 0; mt < 2; mt++) {
        int row = m0 + warp_m * 32 + mt * 16 + g4;
        #pragma unroll
        for (int nt = 0; nt < 4; nt++) {
            int n = warp_n * 32 + nt * 8;
            u16* outp = (n < 64) ? g_qh : (n < 128) ? g_kh : g_vh;
            int col = (n & 63) + 2 * t4;
            *(u32*)&outp[(size_t)row       * Hn + col] =
                pack_h2(acc[mt][nt][0], acc[mt][nt][1]);
            *(u32*)&outp[(size_t)(row + 8) * Hn + col] =
                pack_h2(acc[mt][nt][2], acc[mt][nt][3]);
        }
    }
}

// ---------------------------------------------------------------------------
// Fused causal attention (exact R15 config: (256,3), 13.3us).
// ---------------------------------------------------------------------------
#define ATTN_SMEM (6 * 9216 + 128 * 4)

__global__ __launch_bounds__(256, 3) void attn_f16(float* __restrict__ out)
{
    extern __shared__ __align__(16) char smc[];
    u16* Ks = (u16*)smc;                       // [64][72]
    u16* Qs[2] = { (u16*)(smc + 9216),     (u16*)(smc + 2 * 9216) };
    u16* Vs[2] = { (u16*)(smc + 3 * 9216), (u16*)(smc + 4 * 9216) };
    u16* Ps = (u16*)(smc + 5 * 9216);
    float* pm = (float*)(smc + 6 * 9216);      // [128]

    const int tid  = threadIdx.x;
    const int lane = tid & 31;
    const int wid  = tid >> 5;
    const int warp_m = wid >> 1;        // 0..3
    const int warp_n = wid & 1;         // 0..1
    const int g4 = lane >> 2;
    const int t4 = lane & 3;
    const int r8  = lane & 7;
    const int sel = lane >> 3;
    const int a_row = (sel & 1) * 8 + r8;
    const int a_kof = (sel >> 1) * 8;
    const int bt_krow = (sel & 1) * 8 + r8;
    const int bt_nof  = (sel >> 1) * 8;
    const int bn_row = (sel >> 1) * 8 + r8;
    const int bn_kof = (sel & 1) * 8;

    const int qt = 3 - blockIdx.x;      // heavy tiles first
    const int b  = blockIdx.y;
    const int rowg0 = b * Tn + qt * 64;

    const u32 KsS = sptr(Ks), PsS = sptr(Ps);
    const u32 QsS[2] = { sptr(Qs[0]), sptr(Qs[1]) };
    const u32 VsS[2] = { sptr(Vs[0]), sptr(Vs[1]) };

    const int srow = tid >> 3, scg = tid & 7;

    // ---- prologue: stage K + Q0 + V0 via cp.async ----
    #pragma unroll
    for (int i = 0; i < 2; i++) {
        int r = srow + i * 32;
        u32 o2 = 2u * (r * 72 + scg * 8);
        cpa16(KsS + o2,    g_kh + (size_t)(rowg0 + r) * Hn + scg * 8);
        size_t g0 = (size_t)(b * Tn + r) * Hn + scg * 8;
        cpa16(QsS[0] + o2, g_qh + g0);
        cpa16(VsS[0] + o2, g_vh + g0);
    }
    cpa_commit();
    cpa_wait_all();
    __syncthreads();

    const int r0loc = warp_m * 16 + g4;
    float l0 = 0.f, l1 = 0.f;
    float oacc[4][4];
    #pragma unroll
    for (int nt = 0; nt < 4; nt++)
        #pragma unroll
        for (int e = 0; e < 4; e++) oacc[nt][e] = 0.f;

    for (int st = 0; st <= qt; st++) {
        const int p = st & 1;

        // prefetch next Q/V tile via cp.async (hidden under compute)
        if (st < qt) {
            #pragma unroll
            for (int i = 0; i < 2; i++) {
                int r = srow + i * 32;
                u32 o2 = 2u * (r * 72 + scg * 8);
                size_t g = (size_t)(b * Tn + (st + 1) * 64 + r) * Hn + scg * 8;
                cpa16(QsS[p ^ 1] + o2, g_qh + g);
                cpa16(VsS[p ^ 1] + o2, g_vh + g);
            }
            cpa_commit();
        }

        // ---- S = K . Q^T ----
        float sv[4][4];
        #pragma unroll
        for (int nt = 0; nt < 4; nt++)
            #pragma unroll
            for (int e = 0; e < 4; e++) sv[nt][e] = 0.f;

        #pragma unroll
        for (int ks = 0; ks < 4; ks++) {
            const int k0 = ks * 16;
            u32 a[4];
            u32 aoff = 2u * ((warp_m * 16 + a_row) * 72 + k0 + a_kof);
            ldm4(a[0], a[1], a[2], a[3], KsS + aoff);
            #pragma unroll
            for (int h = 0; h < 2; h++) {
                u32 bq[4];
                u32 boff = 2u * ((warp_n * 32 + h * 16 + bn_row) * 72 + k0 + bn_kof);
                ldm4(bq[0], bq[1], bq[2], bq[3], QsS[p] + boff);
                #pragma unroll
                for (int j = 0; j < 2; j++)
                    mma_f16(sv[h * 2 + j], a, &bq[2 * j]);
            }
        }

        // ---- causal mask on diagonal tile ----
        if (st == qt) {
            #pragma unroll
            for (int nt = 0; nt < 4; nt++) {
                int col = warp_n * 32 + nt * 8 + 2 * t4;
                if (col     > r0loc)     sv[nt][0] = -1e30f;
                if (col + 1 > r0loc)     sv[nt][1] = -1e30f;
                if (col     > r0loc + 8) sv[nt][2] = -1e30f;
                if (col + 1 > r0loc + 8) sv[nt][3] = -1e30f;
            }
        }

        // ---- p = 2^s (fixed m=0), accumulate l, write P ----
        #pragma unroll
        for (int nt = 0; nt < 4; nt++) {
            float p0 = ex2(sv[nt][0]);
            float p1 = ex2(sv[nt][1]);
            float p2 = ex2(sv[nt][2]);
            float p3 = ex2(sv[nt][3]);
            l0 += p0 + p1; l1 += p2 + p3;
            int col = warp_n * 32 + nt * 8 + 2 * t4;
            *(u32*)&Ps[r0loc * 72 + col]       = pack_h2(p0, p1);
            *(u32*)&Ps[(r0loc + 8) * 72 + col] = pack_h2(p2, p3);
        }
        // P visibility within the warp_m pair
        asm volatile("bar.sync %0, %1;" :: "r"(1 + warp_m), "r"(64) : "memory");

        // ---- O += P @ V ----
        #pragma unroll
        for (int ks = 0; ks < 4; ks++) {
            const int k0 = ks * 16;
            u32 a[4];
            u32 aoff = 2u * ((warp_m * 16 + a_row) * 72 + k0 + a_kof);
            ldm4(a[0], a[1], a[2], a[3], PsS + aoff);
            #pragma unroll
            for (int h = 0; h < 2; h++) {
                u32 bv[4];
                u32 boff = 2u * ((k0 + bt_krow) * 72 + warp_n * 32 + h * 16 + bt_nof);
                ldm4t(bv[0], bv[1], bv[2], bv[3], VsS[p] + boff);
                #pragma unroll
                for (int j = 0; j < 2; j++)
                    mma_f16(oacc[h * 2 + j], a, &bv[2 * j]);
            }
        }

        if (st < qt) cpa_wait_all();   // next Q/V landed
        __syncthreads();               // P reads done; buffers consistent
    }

    // ---- epilogue: reduce l across t4 and warp_n, divide, store ----
    l0 += __shfl_xor_sync(0xffffffffu, l0, 1);
    l0 += __shfl_xor_sync(0xffffffffu, l0, 2);
    l1 += __shfl_xor_sync(0xffffffffu, l1, 1);
    l1 += __shfl_xor_sync(0xffffffffu, l1, 2);
    if (t4 == 0) {
        pm[warp_n * 64 + r0loc]     = l0;
        pm[warp_n * 64 + r0loc + 8] = l1;
    }
    __syncthreads();
    float inv0 = 1.f / (pm[r0loc]     + pm[64 + r0loc]);
    float inv1 = 1.f / (pm[r0loc + 8] + pm[64 + r0loc + 8]);

    #pragma unroll
    for (int nt = 0; nt < 4; nt++) {
        int col = warp_n * 32 + nt * 8 + 2 * t4;
        *(float2*)(out + (size_t)(rowg0 + r0loc)     * Hn + col) =
            make_float2(oacc[nt][0] * inv0, oacc[nt][1] * inv0);
        *(float2*)(out + (size_t)(rowg0 + r0loc + 8) * Hn + col) =
            make_float2(oacc[nt][2] * inv1, oacc[nt][3] * inv1);
    }
}

// ---------------------------------------------------------------------------
extern "C" void kernel_launch(void* const* d_in, const int* in_sizes, int n_in,
                              void* d_out, int out_size)
{
    const float* x  = (const float*)d_in[0];
    const float* Wq = (const float*)d_in[1];
    const float* Wk = (const float*)d_in[2];
    const float* Wv = (const float*)d_in[3];
    float* out = (float*)d_out;

    cudaFuncSetAttribute(attn_f16, cudaFuncAttributeMaxDynamicSharedMemorySize, ATTN_SMEM);

    conv_w<<<72, 256>>>(Wq, Wk, Wv);
    qkv_fused<<<512, 384>>>(x);
    attn_f16<<<dim3(4, Bn), 256, ATTN_SMEM>>>(out);
}